// round 16
// baseline (speedup 1.0000x reference)
#include <cuda_runtime.h>
#include <cstdint>

// ActorNetwork_mid_concat — structural rewrite.
// Key identity: feat = [s0|s1|s2|s3|s4|s5]; only s2/s3 (cols 256..1536, 640KB
// of w3) are dynamic across steps. s0 has 7 possible values (init + 6 actions),
// s1/s4 are constant after the first update, s5 is linear in a scalar whose
// 7-step schedule is known at launch. So per step:
//   h = relu(b3 + P0[sel] + P1[st] + P4[st] + x47(s)*u + v + M2@f2 + M3@f3)
// with P0[7],P1[2],P4[2],u,v precomputed once per launch.
// One 8-CTA cluster x 512 threads; M2|M3 (128x1280) register-resident
// (160 cols/CTA, 40 floats/thread); exchange of 128-float partials via DSMEM
// remote stores + cluster.sync (validated in R12). fma.rn.f32x2 for the matvec.
// No global scratch -> graph-replay safe by construction.

#define NCTA  8
#define NTHR  512
#define NSTEP 7

__device__ __forceinline__ uint32_t smem_u32(const void* p) {
    return (uint32_t)__cvta_generic_to_shared(p);
}
__device__ __forceinline__ void st_cluster_f32(uint32_t local_addr, uint32_t rank, float v) {
    uint32_t rem;
    asm volatile("mapa.shared::cluster.u32 %0, %1, %2;" : "=r"(rem) : "r"(local_addr), "r"(rank));
    asm volatile("st.shared::cluster.f32 [%0], %1;" :: "r"(rem), "f"(v) : "memory");
}
__device__ __forceinline__ void cluster_sync() {
    asm volatile("barrier.cluster.arrive.aligned;" ::: "memory");
    asm volatile("barrier.cluster.wait.aligned;" ::: "memory");
}
__device__ __forceinline__ uint32_t ctarank() {
    uint32_t r; asm("mov.u32 %0, %%cluster_ctarank;" : "=r"(r)); return r;
}
__device__ __forceinline__ unsigned long long fma2(unsigned long long a,
                                                   unsigned long long b,
                                                   unsigned long long c) {
    unsigned long long d;
    asm("fma.rn.f32x2 %0, %1, %2, %3;" : "=l"(d) : "l"(a), "l"(b), "l"(c));
    return d;
}
__device__ __forceinline__ float2 unpack2(unsigned long long v) {
    float2 r;
    asm("mov.b64 {%0, %1}, %2;" : "=f"(r.x), "=f"(r.y) : "l"(v));
    return r;
}

__constant__ float VBRC[6] = {300.f, 750.f, 1200.f, 1850.f, 2850.f, 4300.f};

__global__ __launch_bounds__(NTHR, 1) __cluster_dims__(NCTA, 1, 1)
void actor_net_kernel(const float* __restrict__ inp,
                      const float* __restrict__ conv_w, const float* __restrict__ conv_b,
                      const float* __restrict__ w0, const float* __restrict__ b0,
                      const float* __restrict__ w1, const float* __restrict__ b1,
                      const float* __restrict__ w2, const float* __restrict__ b2,
                      const float* __restrict__ w3, const float* __restrict__ b3,
                      const float* __restrict__ w4, const float* __restrict__ b4,
                      float* __restrict__ out)
{
    __shared__ __align__(16) float featc[160];          // this CTA's dynamic feat slice
    __shared__ __align__(16) float part[2][NCTA][128];  // double-buffered partials (DSMEM target)
    // Parena slots: 0..5 = P0[a]; 6 = P0 init; 7/8 = P1 init/steady;
    //               9/10 = P4 init/steady; 11 = u; 12 = v.
    __shared__ __align__(16) float Parena[13][128];     // (DSMEM target)
    __shared__ float cw[512], cb[128];
    __shared__ float w0s[128], b0s[128], w1s[128], b1s[128], w2s[128], b2s[128];
    __shared__ float b3s[128], w4s[768], b4s[8];
    __shared__ float inps[64];
    __shared__ float st2s[8], st3s[8], vcs[6], bws[8], x47v[8];
    __shared__ float lg[6];
    __shared__ int   a_prev_s, steady_s;
    __shared__ __align__(16) float svA[384], svB[128];  // precompute staging

    const int tid = threadIdx.x;
    const uint32_t rank = ctarank();

    // ---- Prologue: load small weights + inputs ----
    for (int i = tid; i < 512; i += NTHR) cw[i] = conv_w[i];
    if (tid < 128) {
        cb[tid]  = conv_b[tid];
        w0s[tid] = w0[tid];  b0s[tid] = b0[tid];
        w1s[tid] = w1[tid];  b1s[tid] = b1[tid];
        w2s[tid] = w2[tid];  b2s[tid] = b2[tid];
        b3s[tid] = b3[tid];
    }
    for (int i = tid; i < 768; i += NTHR) w4s[i] = w4[i];
    if (tid < 6)  b4s[tid] = b4[tid];
    if (tid < 64) inps[tid] = inp[tid];
    if (tid == 0) { a_prev_s = 0; steady_s = 0; }
    __syncthreads();
    if (tid < 6) vcs[tid] = inps[56] * (float)(1 << tid);   // vs * {1,2,4,8,16,32}
    if (tid < 8) { st2s[tid] = inps[16 + tid]; st3s[tid] = inps[24 + tid]; bws[tid] = inps[48 + tid]; }
    __syncthreads();
    // st[4][7] schedule per eval step: [inp[4][7], inp[4][0], c0, c0, c0, c0, c0]
    if (tid < 7) x47v[tid] = (tid == 0) ? inps[39]
                            : (tid == 1) ? inps[32]
                            : vcs[0] / 1000000.0f;

    // ---- Dynamic W slice -> registers ----
    // CTA covers global cols [256 + 160*rank, 256 + 160*rank + 160).
    // thread t: row r = t>>2, quarter q = t&3 -> 40 local cols [q*40, q*40+40).
    const int r = tid >> 2;
    const int q = tid & 3;
    const int base_col = 256 + 160 * (int)rank + q * 40;
    float4 W[10];
    {
        const float4* wp = reinterpret_cast<const float4*>(w3 + (size_t)r * 2048 + base_col);
#pragma unroll
        for (int i = 0; i < 10; i++) W[i] = __ldg(wp + i);
    }

    // ---- Stage precompute source vectors (per-rank jobs) ----
    // jobA: rank<6 -> P0[rank]; rank6 -> P4 init; rank7 -> P4 steady.
    // jobB: rank0 -> P0 init; rank1 -> P1 init; rank2 -> P1 steady;
    //       rank3 -> u (sv=w2); rank4 -> v (sv=b2).
    if (rank < 6) {
        if (tid < 128) {
            const float xa = VBRC[rank] / 4300.0f;
            svA[tid] = fmaxf(fmaf(xa, w0s[tid], b0s[tid]), 0.0f);
            float bv = 0.0f;
            if (rank == 0)      bv = fmaxf(fmaf(inps[7],  w0s[tid], b0s[tid]), 0.0f);
            else if (rank == 1) bv = fmaxf(fmaf(inps[15], w1s[tid], b1s[tid]), 0.0f);
            else if (rank == 2) bv = fmaxf(fmaf(3.0f,     w1s[tid], b1s[tid]), 0.0f);
            else if (rank == 3) bv = w2s[tid];          // u: no relu, no bias
            else if (rank == 4) bv = b2s[tid];          // v
            svB[tid] = bv;
        }
    } else {
        // s4 conv feat: 128 filters x 3 windows over g[0..5]
        if (tid < 384) {
            const int f = tid / 3, k = tid - f * 3;
            float g0 = (rank == 6) ? inps[32 + k]     : vcs[k]     / 1000000.0f;
            float g1 = (rank == 6) ? inps[32 + k + 1] : vcs[k + 1] / 1000000.0f;
            float g2 = (rank == 6) ? inps[32 + k + 2] : vcs[k + 2] / 1000000.0f;
            float g3 = (rank == 6) ? inps[32 + k + 3] : vcs[k + 3] / 1000000.0f;
            float v = cb[f];
            v = fmaf(g0, cw[f * 4 + 0], v);
            v = fmaf(g1, cw[f * 4 + 1], v);
            v = fmaf(g2, cw[f * 4 + 2], v);
            v = fmaf(g3, cw[f * 4 + 3], v);
            svA[f * 3 + k] = fmaxf(v, 0.0f);
        }
    }
    __syncthreads();
    cluster_sync();   // all CTAs live + staged before any remote store

    // ---- Precompute matvecs + broadcast results to all CTAs ----
    {
        // jobA
        int slotA, cbaseA, KA;
        if (rank < 6)      { slotA = (int)rank; cbaseA = 0;    KA = 128; }
        else if (rank == 6){ slotA = 9;         cbaseA = 1536; KA = 384; }
        else               { slotA = 10;        cbaseA = 1536; KA = 384; }
        const int npt = KA / 4;                 // cols per thread (32 or 96)
        const float* wr = w3 + (size_t)r * 2048 + cbaseA + q * npt;
        float sA = 0.0f;
        if (KA == 128) {
#pragma unroll
            for (int i = 0; i < 32; i++) sA = fmaf(__ldg(wr + i), svA[q * 32 + i], sA);
        } else {
#pragma unroll 8
            for (int i = 0; i < 96; i++) sA = fmaf(__ldg(wr + i), svA[q * 96 + i], sA);
        }
        sA += __shfl_xor_sync(0xffffffffu, sA, 1);
        sA += __shfl_xor_sync(0xffffffffu, sA, 2);
        const uint32_t dstA = smem_u32(&Parena[slotA][r]);
        st_cluster_f32(dstA, (uint32_t)q,     sA);
        st_cluster_f32(dstA, (uint32_t)(q + 4), sA);

        // jobB (ranks 0..4)
        if (rank < 5) {
            int slotB, cbaseB;
            if (rank == 0)      { slotB = 6;  cbaseB = 0;    }
            else if (rank == 1) { slotB = 7;  cbaseB = 128;  }
            else if (rank == 2) { slotB = 8;  cbaseB = 128;  }
            else if (rank == 3) { slotB = 11; cbaseB = 1920; }
            else                { slotB = 12; cbaseB = 1920; }
            const float* wrb = w3 + (size_t)r * 2048 + cbaseB + q * 32;
            float sB = 0.0f;
#pragma unroll
            for (int i = 0; i < 32; i++) sB = fmaf(__ldg(wrb + i), svB[q * 32 + i], sB);
            sB += __shfl_xor_sync(0xffffffffu, sB, 1);
            sB += __shfl_xor_sync(0xffffffffu, sB, 2);
            const uint32_t dstB = smem_u32(&Parena[slotB][r]);
            st_cluster_f32(dstB, (uint32_t)q,     sB);
            st_cluster_f32(dstB, (uint32_t)(q + 4), sB);
        }
    }
    cluster_sync();   // Parena complete everywhere

    // Per-CTA conv mapping: ranks 0..3 -> s2 filters 32*rank..+31 (row st2),
    // ranks 4..7 -> s3 filters 32*(rank-4)..+31 (row st3).
    const int f0 = 32 * ((int)rank & 3);
    float* const srow = (rank < 4) ? st2s : st3s;

    // ================= Main loop =================
    for (int s = 0; s < NSTEP; ++s) {
        // ---- Phase A: this CTA's 160 dynamic feat values (32 filters x 5 windows) ----
        if (tid < 160) {
            const int fl = tid / 5, k = tid - fl * 5;
            const int f = f0 + fl;
            float v = cb[f];
            v = fmaf(srow[k],     cw[f * 4 + 0], v);
            v = fmaf(srow[k + 1], cw[f * 4 + 1], v);
            v = fmaf(srow[k + 2], cw[f * 4 + 2], v);
            v = fmaf(srow[k + 3], cw[f * 4 + 3], v);
            featc[tid] = fmaxf(v, 0.0f);
        }
        __syncthreads();

        // ---- Phase B: register matvec over 40 cols via f32x2 FMA ----
        const unsigned long long* Wl = reinterpret_cast<const unsigned long long*>(W);
        const unsigned long long* Fl = reinterpret_cast<const unsigned long long*>(featc + q * 40);
        unsigned long long a0 = 0ull, a1 = 0ull;
#pragma unroll
        for (int i = 0; i < 20; i += 2) {
            a0 = fma2(Wl[i],     Fl[i],     a0);
            a1 = fma2(Wl[i + 1], Fl[i + 1], a1);
        }
        const float2 u0 = unpack2(a0), u1 = unpack2(a1);
        float p = (u0.x + u0.y) + (u1.x + u1.y);
        p += __shfl_xor_sync(0xffffffffu, p, 1);
        p += __shfl_xor_sync(0xffffffffu, p, 2);   // full row-partial over 160 cols

        // ---- Phase C: push partial to all 8 CTAs (2 remote stores/thread) ----
        const int buf = s & 1;
        {
            const uint32_t dst = smem_u32(&part[buf][rank][r]);
            st_cluster_f32(dst, (uint32_t)q,       p);
            st_cluster_f32(dst, (uint32_t)(q + 4), p);
        }
        cluster_sync();   // releases our stores, acquires peers' (double-buffered reuse safe)

        // ---- Phase D: fused h + logits (warps 0..5, one logit each) ----
        const int wid = tid >> 5, lane = tid & 31;
        if (wid < 6) {
            const int st_ = steady_s;
            const int p0slot = st_ ? a_prev_s : 6;
            const float x47 = x47v[s];
            float acc = 0.0f;
#pragma unroll
            for (int jj = 0; jj < 4; jj++) {
                const int i = lane + jj * 32;
                float h = b3s[i] + Parena[p0slot][i] + Parena[7 + st_][i] + Parena[9 + st_][i]
                        + fmaf(x47, Parena[11][i], Parena[12][i]);
#pragma unroll
                for (int c = 0; c < NCTA; c++) h += part[buf][c][i];
                h = fmaxf(h, 0.0f);
                acc = fmaf(w4s[wid * 128 + i], h, acc);
            }
#pragma unroll
            for (int o = 16; o > 0; o >>= 1) acc += __shfl_down_sync(0xffffffffu, acc, o);
            if (lane == 0) lg[wid] = acc + b4s[wid];
        }
        __syncthreads();

        // ---- Phase E: argmax + state update (exact reference arithmetic) ----
        if (s < 6) {
            if (tid == 0) {
                int   a    = 0;
                float best = lg[0];
#pragma unroll
                for (int j = 1; j < 6; j++) if (lg[j] > best) { best = lg[j]; a = j; }
                const float vca   = vcs[a];
                const float delay = vca / bws[s] - 30000.0f;         // BUF
#pragma unroll
                for (int j = 0; j < 7; j++) { st2s[j] = st2s[j + 1]; st3s[j] = st3s[j + 1]; }
                st2s[7] = vca / delay / 1000.0f;
                st3s[7] = delay / 1000.0f / 10.0f;
                a_prev_s = a;
                steady_s = 1;
            }
            __syncthreads();
        } else {
            if (rank == 0 && tid < 6) out[tid] = lg[tid];
        }
    }
}

extern "C" void kernel_launch(void* const* d_in, const int* in_sizes, int n_in,
                              void* d_out, int out_size)
{
    (void)in_sizes; (void)n_in; (void)out_size;
    actor_net_kernel<<<NCTA, NTHR>>>(
        (const float*)d_in[0],  (const float*)d_in[1],  (const float*)d_in[2],
        (const float*)d_in[3],  (const float*)d_in[4],  (const float*)d_in[5],
        (const float*)d_in[6],  (const float*)d_in[7],  (const float*)d_in[8],
        (const float*)d_in[9],  (const float*)d_in[10], (const float*)d_in[11],
        (const float*)d_in[12], (float*)d_out);
}

// round 17
// speedup vs baseline: 2.0247x; 2.0247x over previous
#include <cuda_runtime.h>
#include <cstdint>

// ActorNetwork_mid_concat — R7 transport (16 blocks, L2 monotonic flags) +
// critical-path restructure:
//  * static feat segments (s0/s1/s4/s5): per-step partials precomputed in the
//    prologue (7/2/2 versions + affine in the known x47 schedule), selected
//    post-argmax (identities validated in R16).
//  * dynamic segments (s2/s3): conv windows slide under the state roll, so all
//    k<=3 columns are computed SPECULATIVELY during the flag wait; only k==4
//    columns (appended element, 6 known candidates per step) are completed
//    post-argmax with ~13 predicated FMAs per thread.
// Monotonic flags -> graph-replay safe, no reset.

#define NBLK  16
#define NTHR  256
#define NSTEP 7

__device__ float    g_partial[2][NBLK][128];
__device__ unsigned g_flag[NBLK];   // cumulative step count per block

__device__ __forceinline__ void st_release_u32(unsigned* p, unsigned v) {
    asm volatile("st.release.gpu.global.u32 [%0], %1;" :: "l"(p), "r"(v) : "memory");
}
__device__ __forceinline__ unsigned ld_acquire_u32(const unsigned* p) {
    unsigned v;
    asm volatile("ld.acquire.gpu.global.u32 %0, [%1];" : "=r"(v) : "l"(p) : "memory");
    return v;
}

__constant__ float VBRC[6] = {300.f, 750.f, 1200.f, 1850.f, 2850.f, 4300.f};

// Raw 64-col dot of this thread's W slice against f[0..63] (no shfl).
__device__ __forceinline__ float dot_raw(const float4* Wr, const float* f) {
    const float4* fp = reinterpret_cast<const float4*>(f);
    float4 acc = make_float4(0.f, 0.f, 0.f, 0.f);
#pragma unroll
    for (int i = 0; i < 16; i++) {
        const float4 x = fp[i];
        acc.x = fmaf(Wr[i].x, x.x, acc.x);
        acc.y = fmaf(Wr[i].y, x.y, acc.y);
        acc.z = fmaf(Wr[i].z, x.z, acc.z);
        acc.w = fmaf(Wr[i].w, x.w, acc.w);
    }
    return (acc.x + acc.y) + (acc.z + acc.w);
}

__global__ __launch_bounds__(NTHR, 1)
void actor_net_kernel(const float* __restrict__ inp,
                      const float* __restrict__ conv_w, const float* __restrict__ conv_b,
                      const float* __restrict__ w0, const float* __restrict__ b0,
                      const float* __restrict__ w1, const float* __restrict__ b1,
                      const float* __restrict__ w2, const float* __restrict__ b2,
                      const float* __restrict__ w3, const float* __restrict__ b3,
                      const float* __restrict__ w4, const float* __restrict__ b4,
                      float* __restrict__ out)
{
    __shared__ __align__(16) float featb[128];       // build scratch
    __shared__ __align__(16) float fknown[128];      // speculative feat (k4 cols = 0)
    __shared__ float basearr[128];                   // per-filter k4 window base
    __shared__ float cw[512], cb[128];
    __shared__ float aw[128], ab[128];               // block-specific affine weights
    __shared__ float b3s[128];
    __shared__ float w4s[768], b4s[8];
    __shared__ float stl[8];                         // this block's state row (conv blocks)
    __shared__ float vcs[6], bws[8], dtab[36], x47v[8], gv[8];
    __shared__ float pv0sm[6][128];                  // block 0: 6 action partials
    __shared__ float hbuf[128], lg[6];
    __shared__ unsigned sbase;

    const int tid = threadIdx.x;
    const int bid = blockIdx.x;
    const int r    = tid >> 1;
    const int half = tid & 1;

    const bool is_conv = (bid >= 2 && bid <= 11);
    const bool is_s2   = (bid <= 6);
    const bool is_s4   = (bid >= 12 && bid <= 14);

    // ================= Prologue: loads =================
    if (is_conv || is_s4) {
        for (int i = tid; i < 512; i += NTHR) cw[i] = conv_w[i];
        if (tid < 128) cb[tid] = conv_b[tid];
    }
    if (tid < 128) {
        if (bid == 0)       { aw[tid] = w0[tid]; ab[tid] = b0[tid]; }
        else if (bid == 1)  { aw[tid] = w1[tid]; ab[tid] = b1[tid]; }
        else if (bid == 15) { aw[tid] = w2[tid]; ab[tid] = b2[tid]; }
        b3s[tid] = b3[tid];
    }
    for (int i = tid; i < 768; i += NTHR) w4s[i] = w4[i];
    if (tid < 6)  b4s[tid] = b4[tid];
    if (tid < 6)  vcs[tid] = __ldg(inp + 56) * (float)(1 << tid);
    if (tid < 8)  bws[tid] = __ldg(inp + 48 + tid);
    if (is_conv && tid < 8) stl[tid] = __ldg(inp + (is_s2 ? 16 : 24) + tid);
    if (tid == 0) sbase = ld_acquire_u32(&g_flag[bid]);

    // w3 slice -> registers (row r, 64 cols per thread)
    const int colbase = bid * 128 + half * 64;
    float4 W[16];
    {
        const float4* wp = reinterpret_cast<const float4*>(w3 + (size_t)r * 2048 + colbase);
#pragma unroll
        for (int i = 0; i < 16; i++) W[i] = __ldg(wp + i);
    }
    __syncthreads();

    // δ tables + x47 schedule (need vcs/bws)
    if (is_conv && tid < 36) {
        const int i = tid / 6, a = tid - i * 6;
        const float vca   = vcs[a];
        const float delay = vca / bws[i] - 30000.0f;
        dtab[tid] = is_s2 ? (vca / delay / 1000.0f) : (delay / 1000.0f / 10.0f);
    }
    if (bid == 15 && tid < 7)
        x47v[tid] = (tid == 0) ? __ldg(inp + 39)
                  : (tid == 1) ? __ldg(inp + 32)
                  : vcs[0] / 1000000.0f;

    // k4 column gather (conv blocks): Wk4 / filter ids / cw3 into registers
    int   nk4 = 0;
    int   fk4i[13];
    float Wk4[13], cw3k[13];
    const int segbase = colbase - (is_s2 ? 256 : 896);   // segment-local first col
    if (is_conv) {
        int c0 = (4 - (segbase % 5)) % 5;                // first c with k==4
#pragma unroll
        for (int i = 0; i < 13; i++) {
            const int c = c0 + 5 * i;
            if (c < 64) {
                const int f = (segbase + c) / 5;
                fk4i[i] = f;
                Wk4[i]  = __ldg(w3 + (size_t)r * 2048 + colbase + c);
                cw3k[i] = cw[f * 4 + 3];
                nk4 = i + 1;
            } else { fk4i[i] = 0; Wk4[i] = 0.f; cw3k[i] = 0.f; }
        }
    }
    __syncthreads();
    const unsigned base = sbase;

    // ================= Prologue: precompute partials =================
    float pcur = 0.f;        // partial for eval 0
    float psteadyR = 0.f;    // blocks 1, 12..14
    float puR = 0.f, pvR = 0.f;  // block 15

    if (bid == 0) {
        if (tid < 128) featb[tid] = fmaxf(fmaf(__ldg(inp + 7), aw[tid], ab[tid]), 0.f);
        __syncthreads();
        { float p = dot_raw(W, featb + half * 64); p += __shfl_xor_sync(~0u, p, 1); pcur = p; }
        for (int v = 0; v < 6; v++) {
            __syncthreads();
            if (tid < 128) featb[tid] = fmaxf(fmaf(VBRC[v] / 4300.0f, aw[tid], ab[tid]), 0.f);
            __syncthreads();
            float p = dot_raw(W, featb + half * 64); p += __shfl_xor_sync(~0u, p, 1);
            if (half == 0) pv0sm[v][r] = p;
        }
        __syncthreads();
    } else if (bid == 1) {
        if (tid < 128) featb[tid] = fmaxf(fmaf(__ldg(inp + 15), aw[tid], ab[tid]), 0.f);
        __syncthreads();
        { float p = dot_raw(W, featb + half * 64); p += __shfl_xor_sync(~0u, p, 1); pcur = p; }
        __syncthreads();
        if (tid < 128) featb[tid] = fmaxf(fmaf(3.0f, aw[tid], ab[tid]), 0.f);
        __syncthreads();
        { float p = dot_raw(W, featb + half * 64); p += __shfl_xor_sync(~0u, p, 1); psteadyR = p; }
    } else if (is_s4) {
        for (int v = 0; v < 2; v++) {
            if (tid < 6) gv[tid] = (v == 0) ? __ldg(inp + 32 + tid) : vcs[tid] / 1000000.0f;
            __syncthreads();
            if (tid < 128) {
                const int sc = bid * 128 + tid - 1536;
                const int f = sc / 3, k = sc - f * 3;
                float x = cb[f];
                x = fmaf(gv[k],     cw[f * 4 + 0], x);
                x = fmaf(gv[k + 1], cw[f * 4 + 1], x);
                x = fmaf(gv[k + 2], cw[f * 4 + 2], x);
                x = fmaf(gv[k + 3], cw[f * 4 + 3], x);
                featb[tid] = fmaxf(x, 0.f);
            }
            __syncthreads();
            float p = dot_raw(W, featb + half * 64); p += __shfl_xor_sync(~0u, p, 1);
            if (v == 0) pcur = p; else psteadyR = p;
            __syncthreads();
        }
    } else if (bid == 15) {
        if (tid < 128) featb[tid] = aw[tid];          // w2 raw
        __syncthreads();
        { float p = dot_raw(W, featb + half * 64); p += __shfl_xor_sync(~0u, p, 1); puR = p; }
        __syncthreads();
        if (tid < 128) featb[tid] = ab[tid];          // b2 raw
        __syncthreads();
        { float p = dot_raw(W, featb + half * 64); p += __shfl_xor_sync(~0u, p, 1); pvR = p; }
        pcur = fmaf(x47v[0], puR, pvR);
    } else {
        // conv blocks: eval-0 feat directly from initial state
        if (tid < 128) {
            const int sc = bid * 128 + tid - (is_s2 ? 256 : 896);
            const int f = sc / 5, k = sc - f * 5;
            float x = cb[f];
            x = fmaf(stl[k],     cw[f * 4 + 0], x);
            x = fmaf(stl[k + 1], cw[f * 4 + 1], x);
            x = fmaf(stl[k + 2], cw[f * 4 + 2], x);
            x = fmaf(stl[k + 3], cw[f * 4 + 3], x);
            featb[tid] = fmaxf(x, 0.f);
        }
        __syncthreads();
        { float p = dot_raw(W, featb + half * 64); p += __shfl_xor_sync(~0u, p, 1); pcur = p; }
    }
    __syncthreads();

    // ================= Main loop: evals 0..6 =================
    for (int e = 0; e < NSTEP; ++e) {
        const int buf = e & 1;
        if (half == 0) __stcg(&g_partial[buf][bid][r], pcur);
        __syncthreads();                                       // all STGs issued
        const unsigned target = base + (unsigned)e + 1u;
        if (tid == 0) st_release_u32(&g_flag[bid], target);

        // ---- Speculative feat for eval e+1 (during the wait) ----
        if (e < 6 && is_conv && tid < 128) {
            const int sc = bid * 128 + tid - (is_s2 ? 256 : 896);
            const int f = sc / 5, k = sc - f * 5;
            float val = 0.f;
            if (k < 4) {                                       // shifted window, fully known
                float x = cb[f];
                x = fmaf(stl[k + 1], cw[f * 4 + 0], x);
                x = fmaf(stl[k + 2], cw[f * 4 + 1], x);
                x = fmaf(stl[k + 3], cw[f * 4 + 2], x);
                x = fmaf(stl[k + 4], cw[f * 4 + 3], x);
                val = fmaxf(x, 0.f);
            }
            fknown[tid] = val;
            // k4 window base over stn[4..6] = stl[5..7]
            float b = cb[tid];
            b = fmaf(stl[5], cw[tid * 4 + 0], b);
            b = fmaf(stl[6], cw[tid * 4 + 1], b);
            b = fmaf(stl[7], cw[tid * 4 + 2], b);
            basearr[tid] = b;
        }
        __syncthreads();
        float acck = 0.f;
        if (e < 6 && is_conv) acck = dot_raw(W, fknown + half * 64);

        // ---- Wait for all blocks ----
        if (tid < NBLK) {
            while ((int)(ld_acquire_u32(&g_flag[tid]) - target) < 0) { /* spin */ }
        }
        __syncthreads();

        // ---- Reduce -> h ----
        if (tid < 128) {
            float a = b3s[tid];
#pragma unroll
            for (int b = 0; b < NBLK; b++) a += __ldcg(&g_partial[buf][b][tid]);
            hbuf[tid] = fmaxf(a, 0.0f);
        }
        __syncthreads();

        // ---- Logits ----
        if (tid < 192) {
            const int a = tid >> 5, l = tid & 31;
            float v = 0.0f;
            v = fmaf(w4s[a * 128 + l],      hbuf[l],      v);
            v = fmaf(w4s[a * 128 + l + 32], hbuf[l + 32], v);
            v = fmaf(w4s[a * 128 + l + 64], hbuf[l + 64], v);
            v = fmaf(w4s[a * 128 + l + 96], hbuf[l + 96], v);
#pragma unroll
            for (int o = 16; o > 0; o >>= 1) v += __shfl_down_sync(0xffffffffu, v, o);
            if (l == 0) lg[a] = v + b4s[a];
        }
        __syncthreads();

        // ---- Argmax + next partial (tiny completion) ----
        if (e < 6) {
            int   a    = 0;
            float best = lg[0];
#pragma unroll
            for (int j = 1; j < 6; j++) if (lg[j] > best) { best = lg[j]; a = j; }

            float p;
            if (is_conv) {
                const float d = dtab[e * 6 + a];
                p = acck;
#pragma unroll
                for (int i = 0; i < 13; i++) {
                    if (i < nk4) {
                        const float val = fmaxf(fmaf(d, cw3k[i], basearr[fk4i[i]]), 0.f);
                        p = fmaf(Wk4[i], val, p);
                    }
                }
                p += __shfl_xor_sync(~0u, p, 1);
                if (tid == 0) {                       // roll + append (next spec input)
                    float rr[8];
#pragma unroll
                    for (int j = 0; j < 8; j++) rr[j] = stl[j];
#pragma unroll
                    for (int j = 0; j < 7; j++) stl[j] = rr[j + 1];
                    stl[7] = d;
                }
            } else if (bid == 0) {
                p = pv0sm[a][r];
            } else if (bid == 15) {
                p = fmaf(x47v[e + 1], puR, pvR);
            } else {
                p = psteadyR;                         // blocks 1, 12..14
            }
            pcur = p;
            __syncthreads();                          // stl update / lg reuse fence
        } else {
            if (bid == 0 && tid < 6) out[tid] = lg[tid];
        }
    }
}

extern "C" void kernel_launch(void* const* d_in, const int* in_sizes, int n_in,
                              void* d_out, int out_size)
{
    (void)in_sizes; (void)n_in; (void)out_size;
    actor_net_kernel<<<NBLK, NTHR>>>(
        (const float*)d_in[0],  (const float*)d_in[1],  (const float*)d_in[2],
        (const float*)d_in[3],  (const float*)d_in[4],  (const float*)d_in[5],
        (const float*)d_in[6],  (const float*)d_in[7],  (const float*)d_in[8],
        (const float*)d_in[9],  (const float*)d_in[10], (const float*)d_in[11],
        (const float*)d_in[12], (float*)d_out);
}